// round 17
// baseline (speedup 1.0000x reference)
#include <cuda_runtime.h>
#include <cuda_fp16.h>
#include <mma.h>
#include <stdint.h>

using namespace nvcuda;

// GCN_57501022159512: 2-layer GCN, N=100000 nodes, E=1600000 edges, 64 -> 128 -> 128.
// h1 = relu(gcnconv(x, W1, b1)); t = batchnorm(h1); out = relu(gcnconv(t, W2, b2))
//
// R17: the 5-kernel setup chain (zero/detect, deg, scanA, scanC, fillcsr) is
// collapsed into ONE 148-block resident kernel with a sense-reversing software
// grid barrier (4 barriers, even count -> barrier state self-restores each
// graph replay). Compute kernels unchanged from R16.

#define NNODES 100000
#define NEDGES 1600000
#define FIN    64
#define FHID   128
#define BN_EPS 1e-5f

#define MPAD   100032          // NNODES rounded up to 64 (MMA M-tiles)

#define NBLK        148        // one block per SM -> all resident, barrier safe
#define COOP_THREADS 256
#define NPB         676        // ceil(NNODES / NBLK); 148*676 = 100048

#define TLD 132                // padded smem ldm for fp32 acc staging

// ---------------- scratch (device globals; no allocs allowed) ----------------
__device__ __half  g_xh  [NNODES * FIN];       // x in fp16
__device__ __half  g_aggx[MPAD * FIN];         // agg(x) in fp16 (padded, pad=0)
__device__ __half  g_th  [MPAD * FHID];        // t = relu(aggx@W1+b1), fp16
__device__ __half2 g_h2  [MPAD * (FHID / 2)];  // bn(t) @ W2 (fp16, padded)
__device__ __half  g_W1h[FIN * FHID];          // W1 in fp16 (row-major K x N)
__device__ __half  g_W2h[FHID * FHID];         // W2 in fp16 (row-major K x N)
__device__ float   g_dinv[NNODES];
__device__ int     g_deg [NNODES];
__device__ float   g_stats[2 * FHID];          // sum,sumsq
__device__ int     g_off [NNODES + 1];         // CSR offsets (by destination col)
__device__ int     g_cursor[NNODES];           // placement cursors
__device__ int2    g_csr[NEDGES];              // (src row, norm bits) sorted by dest
__device__ int     g_bsum[NBLK];               // per-block degree sums
__device__ int     g_barcount = 0;             // grid barrier state (self-restoring)
__device__ int     g_barsense = 0;

// ---------------- helpers ----------------

__device__ __forceinline__ void h16_to_f8(uint4 u, float4& a, float4& b) {
    const float2 f0 = __half22float2(*reinterpret_cast<__half2*>(&u.x));
    const float2 f1 = __half22float2(*reinterpret_cast<__half2*>(&u.y));
    const float2 f2 = __half22float2(*reinterpret_cast<__half2*>(&u.z));
    const float2 f3 = __half22float2(*reinterpret_cast<__half2*>(&u.w));
    a = make_float4(f0.x, f0.y, f1.x, f1.y);
    b = make_float4(f2.x, f2.y, f3.x, f3.y);
}

__device__ __forceinline__ uint4 f8_to_h16(float4 a, float4 b) {
    uint4 u;
    __half2 h0 = __floats2half2_rn(a.x, a.y);
    __half2 h1 = __floats2half2_rn(a.z, a.w);
    __half2 h2 = __floats2half2_rn(b.x, b.y);
    __half2 h3 = __floats2half2_rn(b.z, b.w);
    u.x = *reinterpret_cast<uint32_t*>(&h0);
    u.y = *reinterpret_cast<uint32_t*>(&h1);
    u.z = *reinterpret_cast<uint32_t*>(&h2);
    u.w = *reinterpret_cast<uint32_t*>(&h3);
    return u;
}

__device__ __forceinline__ void fma8(float4& a0, float4& a1, uint4 u, float nm) {
    float4 v0, v1;
    h16_to_f8(u, v0, v1);
    a0.x = fmaf(v0.x, nm, a0.x); a0.y = fmaf(v0.y, nm, a0.y);
    a0.z = fmaf(v0.z, nm, a0.z); a0.w = fmaf(v0.w, nm, a0.w);
    a1.x = fmaf(v1.x, nm, a1.x); a1.y = fmaf(v1.y, nm, a1.y);
    a1.z = fmaf(v1.z, nm, a1.z); a1.w = fmaf(v1.w, nm, a1.w);
}

__device__ __forceinline__ int load_idx(const void* ei, int pos, bool is64) {
    int v = is64 ? (int)((const long long*)ei)[pos] : ((const int*)ei)[pos];
    return min(max(v, 0), NNODES - 1);
}

// Sense-reversing grid barrier; all NBLK blocks are resident (NBLK <= #SMs).
// State self-restores after an EVEN number of uses per launch (we use 4).
__device__ __forceinline__ void grid_barrier(int* s_sense) {
    __syncthreads();
    if (threadIdx.x == 0) {
        const int s = *s_sense;
        __threadfence();
        if (atomicAdd(&g_barcount, 1) == NBLK - 1) {
            g_barcount = 0;                 // safe: all arrived; they spin on sense
            __threadfence();
            atomicExch(&g_barsense, 1 - s);
        } else {
            while (atomicAdd(&g_barsense, 0) == s) { }
        }
        __threadfence();
        *s_sense = 1 - s;
    }
    __syncthreads();
}

// ---------------- fused setup: zero/convert/detect -> deg -> scan -> fillcsr --
__global__ void __launch_bounds__(COOP_THREADS) k_setup(const float* __restrict__ x,
                                                        const float* __restrict__ W1,
                                                        const float* __restrict__ W2,
                                                        const void* __restrict__ ei) {
    __shared__ int s_sense;
    __shared__ int s_is64;
    __shared__ int red[COOP_THREADS];
    __shared__ int partial[COOP_THREADS];
    __shared__ int s_base;

    const int tid = threadIdx.x;
    const int gidx = blockIdx.x * COOP_THREADS + tid;
    const int gstride = NBLK * COOP_THREADS;
    if (tid == 0) s_sense = 0;

    // ---- P0: zero + convert + local dtype detect ----
    for (int j = gidx; j < NNODES; j += gstride) g_deg[j] = 0;
    if (gidx < 2 * FHID) g_stats[gidx] = 0.f;
    for (int j = gidx; j < FIN * FHID; j += gstride)  g_W1h[j] = __float2half_rn(W1[j]);
    for (int j = gidx; j < FHID * FHID; j += gstride) g_W2h[j] = __float2half_rn(W2[j]);
    for (int j = gidx; j < (MPAD - NNODES) * FIN; j += gstride)
        g_aggx[NNODES * FIN + j] = __float2half_rn(0.f);
    {   // x -> fp16, 8 floats per iteration
        const float4* x4 = reinterpret_cast<const float4*>(x);
        uint4* xh4 = reinterpret_cast<uint4*>(g_xh);
        for (int j = gidx; j < NNODES * FIN / 8; j += gstride) {
            const float4 a = x4[2 * j];
            const float4 b = x4[2 * j + 1];
            xh4[j] = f8_to_h16(a, b);
        }
    }
    {   // per-block dtype detect (no cross-block communication needed)
        __shared__ int bad;
        if (tid == 0) bad = 0;
        __syncthreads();
        const int* w = (const int*)ei;
        for (int j = tid; j < 1024; j += COOP_THREADS) {
            const int lo = w[2 * j], hi = w[2 * j + 1];
            if (hi != 0 || lo < 0 || lo >= NNODES) bad = 1;
        }
        __syncthreads();
        if (tid == 0) s_is64 = (bad == 0) ? 1 : 0;
        __syncthreads();
    }
    const bool is64 = (s_is64 != 0);

    grid_barrier(&s_sense);   // B1

    // ---- P1: degree count ----
    for (int e = gidx; e < NEDGES; e += gstride)
        atomicAdd(&g_deg[load_idx(ei, NEDGES + e, is64)], 1);

    grid_barrier(&s_sense);   // B2

    // ---- P2a: per-block degree sums ----
    const int beg = blockIdx.x * NPB;
    const int end = min(beg + NPB, NNODES);
    {
        int s = 0;
        for (int i = beg + tid; i < end; i += COOP_THREADS) s += g_deg[i];
        red[tid] = s;
        __syncthreads();
        for (int d = 128; d > 0; d >>= 1) {
            if (tid < d) red[tid] += red[tid + d];
            __syncthreads();
        }
        if (tid == 0) g_bsum[blockIdx.x] = red[0];
    }

    grid_barrier(&s_sense);   // B3

    // ---- P2b: offsets + cursors + dinv ----
    {
        int v = (tid < blockIdx.x) ? g_bsum[tid] : 0;   // NBLK <= 256
        red[tid] = v;
        __syncthreads();
        for (int d = 128; d > 0; d >>= 1) {
            if (tid < d) red[tid] += red[tid + d];
            __syncthreads();
        }
        if (tid == 0) s_base = red[0];
        __syncthreads();

        const int cbeg = beg + tid * 3;                 // 256*3 >= NPB
        int dloc[3];
        int csum = 0;
#pragma unroll
        for (int j = 0; j < 3; j++) {
            const int i = cbeg + j;
            dloc[j] = (i < end) ? g_deg[i] : 0;
            csum += dloc[j];
        }
        partial[tid] = csum;
        __syncthreads();
        for (int d = 1; d < 256; d <<= 1) {
            int v2 = (tid >= d) ? partial[tid - d] : 0;
            __syncthreads();
            partial[tid] += v2;
            __syncthreads();
        }
        int run = s_base + ((tid == 0) ? 0 : partial[tid - 1]);
#pragma unroll
        for (int j = 0; j < 3; j++) {
            const int i = cbeg + j;
            if (i < end) {
                g_off[i] = run;
                g_cursor[i] = run;
                g_dinv[i] = rsqrtf((float)(dloc[j] + 1));
                run += dloc[j];
            }
        }
        if (blockIdx.x == NBLK - 1 && tid == 0)
            g_off[NNODES] = s_base + g_bsum[NBLK - 1];
    }

    grid_barrier(&s_sense);   // B4 (4 total -> barrier state restored)

    // ---- P3: counting sort into CSR ----
    for (int e = gidx; e < NEDGES; e += gstride) {
        const int r = load_idx(ei, e, is64);
        const int c = load_idx(ei, NEDGES + e, is64);
        const int pos = atomicAdd(&g_cursor[c], 1);
        const float nm = g_dinv[r] * g_dinv[c];
        g_csr[pos] = make_int2(r, __float_as_int(nm));
    }
}

// ---------------- gather over x: 8-lane virtual warps, uint4, unroll x4 ------
__global__ void __launch_bounds__(256) k_gather_x() {
    const int lane = threadIdx.x & 7;
    const int vw   = (blockIdx.x * blockDim.x + threadIdx.x) >> 3;
    const int nvw  = (gridDim.x * blockDim.x) >> 3;
    const uint4* xp = reinterpret_cast<const uint4*>(g_xh);
    uint4* ap = reinterpret_cast<uint4*>(g_aggx);

    for (int c = vw; c < NNODES; c += nvw) {
        const int beg = g_off[c], end = g_off[c + 1];
        const float dc = g_dinv[c];
        const float d2 = dc * dc;
        float4 h0, h1;
        h16_to_f8(xp[(size_t)c * 8 + lane], h0, h1);
        float4 a0 = make_float4(h0.x * d2, h0.y * d2, h0.z * d2, h0.w * d2);
        float4 a1 = make_float4(h1.x * d2, h1.y * d2, h1.z * d2, h1.w * d2);
        int i = beg;
        for (; i + 4 <= end; i += 4) {
            const int2 e0 = g_csr[i];
            const int2 e1 = g_csr[i + 1];
            const int2 e2 = g_csr[i + 2];
            const int2 e3 = g_csr[i + 3];
            const uint4 u0 = xp[(size_t)e0.x * 8 + lane];
            const uint4 u1 = xp[(size_t)e1.x * 8 + lane];
            const uint4 u2 = xp[(size_t)e2.x * 8 + lane];
            const uint4 u3 = xp[(size_t)e3.x * 8 + lane];
            fma8(a0, a1, u0, __int_as_float(e0.y));
            fma8(a0, a1, u1, __int_as_float(e1.y));
            fma8(a0, a1, u2, __int_as_float(e2.y));
            fma8(a0, a1, u3, __int_as_float(e3.y));
        }
        for (; i < end; i++) {
            const int2 en = g_csr[i];
            fma8(a0, a1, xp[(size_t)en.x * 8 + lane], __int_as_float(en.y));
        }
        ap[(size_t)c * 8 + lane] = f8_to_h16(a0, a1);
    }
}

// ---------------- gemm1t: t = relu(aggx @ W1 + b1), fused BN stats -----------
__global__ void __launch_bounds__(256) k_gemm1t(const float* __restrict__ b1) {
    __shared__ float sT[64 * TLD];          // 33.8 KB fp32 acc staging
    __shared__ float p0[2][FHID], p1[2][FHID];
    const int t = threadIdx.x;
    const int warp = t >> 5;
    const int base = blockIdx.x * 64;

    wmma::fragment<wmma::matrix_b, 16, 16, 16, __half, wmma::row_major> bf[4];
#pragma unroll
    for (int k = 0; k < 4; k++)
        wmma::load_matrix_sync(bf[k], g_W1h + (k * 16) * FHID + warp * 16, FHID);

#pragma unroll
    for (int m = 0; m < 4; m++) {
        wmma::fragment<wmma::accumulator, 16, 16, 16, float> acc;
        wmma::fill_fragment(acc, 0.0f);
#pragma unroll
        for (int k = 0; k < 4; k++) {
            wmma::fragment<wmma::matrix_a, 16, 16, 16, __half, wmma::row_major> af;
            wmma::load_matrix_sync(af, g_aggx + (size_t)(base + m * 16) * FIN + k * 16, FIN);
            wmma::mma_sync(acc, af, bf[k], acc);
        }
        wmma::store_matrix_sync(sT + (m * 16) * TLD + warp * 16, acc, TLD,
                                wmma::mem_row_major);
    }
    __syncthreads();

    const int col = t & 127;
    const int half = t >> 7;
    const float bb = b1[col];
    float s = 0.f, ss = 0.f;
#pragma unroll 4
    for (int j = 0; j < 32; j++) {
        const int row = half * 32 + j;
        const int r = base + row;
        float v = sT[row * TLD + col];
        v = fmaxf(v + bb, 0.f);
        g_th[(size_t)r * FHID + col] = __float2half_rn(v);
        if (r < NNODES) { s += v; ss += v * v; }
    }
    p0[half][col] = s;
    p1[half][col] = ss;
    __syncthreads();
    if (half == 0) {
        atomicAdd(&g_stats[col], p0[0][col] + p0[1][col]);
        atomicAdd(&g_stats[FHID + col], p1[0][col] + p1[1][col]);
    }
}

// ---------------- GEMM2 on tensor cores (fp16 t in, fp16 h2 out) -------------
__global__ void __launch_bounds__(256) k_gemm2_mma(const float* __restrict__ gamma,
                                                   const float* __restrict__ beta) {
    __shared__ __half  sA[64 * FHID];       // 16 KB
    __shared__ float   sScale[FHID], sShift[FHID];
    const int t = threadIdx.x;
    const int warp = t >> 5;
    const int base = blockIdx.x * 64;

    if (t < FHID) {
        const float inv_n = 1.0f / (float)NNODES;
        const float mean = g_stats[t] * inv_n;
        const float var  = g_stats[FHID + t] * inv_n - mean * mean;
        const float rstd = rsqrtf(var + BN_EPS);
        const float sc = gamma[t] * rstd;
        sScale[t] = sc;
        sShift[t] = beta[t] - mean * sc;
    }
    __syncthreads();

    for (int i = t; i < 64 * FHID; i += 256) {
        const int c = i & 127;
        const float v = __half2float(g_th[(size_t)(base + (i >> 7)) * FHID + c]);
        sA[i] = __float2half_rn(fmaf(v, sScale[c], sShift[c]));
    }
    __syncthreads();

    wmma::fragment<wmma::matrix_b, 16, 16, 16, __half, wmma::row_major> bf[8];
#pragma unroll
    for (int k = 0; k < 8; k++)
        wmma::load_matrix_sync(bf[k], g_W2h + (k * 16) * FHID + warp * 16, FHID);

    __half* h2 = reinterpret_cast<__half*>(g_h2);
#pragma unroll
    for (int m = 0; m < 4; m++) {
        wmma::fragment<wmma::accumulator, 16, 16, 16, float> acc;
        wmma::fill_fragment(acc, 0.0f);
#pragma unroll
        for (int k = 0; k < 8; k++) {
            wmma::fragment<wmma::matrix_a, 16, 16, 16, __half, wmma::row_major> af;
            wmma::load_matrix_sync(af, sA + (m * 16) * FHID + k * 16, FHID);
            wmma::mma_sync(acc, af, bf[k], acc);
        }
        wmma::fragment<wmma::accumulator, 16, 16, 16, __half> hacc;
#pragma unroll
        for (int i = 0; i < acc.num_elements; i++)
            hacc.x[i] = __float2half_rn(acc.x[i]);
        wmma::store_matrix_sync(h2 + (size_t)(base + m * 16) * FHID + warp * 16,
                                hacc, FHID, wmma::mem_row_major);
    }
}

// ---------------- gather2: 16-lane virtual warps, uint4 rows, unroll x4 ------
__global__ void __launch_bounds__(256) k_gather2(float* __restrict__ out,
                                                 const float* __restrict__ b2) {
    const int lane = threadIdx.x & 15;
    const int vw   = (blockIdx.x * blockDim.x + threadIdx.x) >> 4;
    const int nvw  = (gridDim.x * blockDim.x) >> 4;
    const float4 bf0 = reinterpret_cast<const float4*>(b2)[2 * lane];
    const float4 bf1 = reinterpret_cast<const float4*>(b2)[2 * lane + 1];
    const uint4* hp = reinterpret_cast<const uint4*>(g_h2);
    float4* o4 = reinterpret_cast<float4*>(out);

    for (int c = vw; c < NNODES; c += nvw) {
        const int beg = g_off[c], end = g_off[c + 1];
        const float dc = g_dinv[c];
        const float d2 = dc * dc;
        float4 h0, h1;
        h16_to_f8(hp[(size_t)c * 16 + lane], h0, h1);
        float4 a0 = make_float4(h0.x * d2, h0.y * d2, h0.z * d2, h0.w * d2);
        float4 a1 = make_float4(h1.x * d2, h1.y * d2, h1.z * d2, h1.w * d2);
        int i = beg;
        for (; i + 4 <= end; i += 4) {
            const int2 e0 = g_csr[i];
            const int2 e1 = g_csr[i + 1];
            const int2 e2 = g_csr[i + 2];
            const int2 e3 = g_csr[i + 3];
            const uint4 u0 = hp[(size_t)e0.x * 16 + lane];
            const uint4 u1 = hp[(size_t)e1.x * 16 + lane];
            const uint4 u2 = hp[(size_t)e2.x * 16 + lane];
            const uint4 u3 = hp[(size_t)e3.x * 16 + lane];
            fma8(a0, a1, u0, __int_as_float(e0.y));
            fma8(a0, a1, u1, __int_as_float(e1.y));
            fma8(a0, a1, u2, __int_as_float(e2.y));
            fma8(a0, a1, u3, __int_as_float(e3.y));
        }
        for (; i < end; i++) {
            const int2 en = g_csr[i];
            fma8(a0, a1, hp[(size_t)en.x * 16 + lane], __int_as_float(en.y));
        }
        a0.x = fmaxf(a0.x + bf0.x, 0.f); a0.y = fmaxf(a0.y + bf0.y, 0.f);
        a0.z = fmaxf(a0.z + bf0.z, 0.f); a0.w = fmaxf(a0.w + bf0.w, 0.f);
        a1.x = fmaxf(a1.x + bf1.x, 0.f); a1.y = fmaxf(a1.y + bf1.y, 0.f);
        a1.w = fmaxf(a1.w + bf1.w, 0.f); a1.z = fmaxf(a1.z + bf1.z, 0.f);
        o4[(size_t)c * 32 + 2 * lane]     = a0;
        o4[(size_t)c * 32 + 2 * lane + 1] = a1;
    }
}

// ---------------- launch ----------------
extern "C" void kernel_launch(void* const* d_in, const int* in_sizes, int n_in,
                              void* d_out, int out_size) {
    const float* x     = (const float*)d_in[0];
    const void*  ei    = d_in[1];                 // [2, E], int32 OR int64 (detected)
    const float* W1    = (const float*)d_in[2];
    const float* b1    = (const float*)d_in[3];
    const float* gamma = (const float*)d_in[4];
    const float* beta  = (const float*)d_in[5];
    const float* W2    = (const float*)d_in[6];
    const float* b2    = (const float*)d_in[7];
    float* out = (float*)d_out;

    k_setup<<<NBLK, COOP_THREADS>>>(x, W1, W2, ei);
    k_gather_x<<<1184, 256>>>();
    k_gemm1t<<<MPAD / 64, 256>>>(b1);
    k_gemm2_mma<<<MPAD / 64, 256>>>(gamma, beta);
    k_gather2<<<1184, 256>>>(out, b2);
}